// round 1
// baseline (speedup 1.0000x reference)
#include <cuda_runtime.h>

// GCN symmetric-normalized CSR aggregation.
// out[d, :] = rsqrt(deg[d]) * sum_{e in row d} rsqrt(deg[col[e]]) * feat[col[e], :]
//
// One warp per destination node. Each lane owns a float2 slice of the
// 64-float feature vector, so every edge gather is one coalesced 256B row.

#define FEAT 64
#define WARPS_PER_BLOCK 8
#define THREADS (WARPS_PER_BLOCK * 32)

__global__ __launch_bounds__(THREADS) void gcn_agg_kernel(
    const int* __restrict__ row_ptr,
    const int* __restrict__ col_idx,
    const float* __restrict__ node_feat,
    const float* __restrict__ degrees,
    float* __restrict__ out,
    int n_nodes)
{
    const int warp_id = (blockIdx.x * WARPS_PER_BLOCK) + (threadIdx.x >> 5);
    const int lane = threadIdx.x & 31;
    if (warp_id >= n_nodes) return;

    const int start = __ldg(&row_ptr[warp_id]);
    const int end   = __ldg(&row_ptr[warp_id + 1]);

    float accx = 0.0f, accy = 0.0f;

    int e = start;
    // Software-pipelined by 2: overlap the col_idx/degree fetch for the next
    // edge with the feature gather of the current one.
    if (e < end) {
        int s0 = __ldg(&col_idx[e]);
        float ns0 = rsqrtf(__ldg(&degrees[s0]));
        while (e + 1 < end) {
            int s1 = __ldg(&col_idx[e + 1]);
            float ns1 = rsqrtf(__ldg(&degrees[s1]));
            const float2 v0 = __ldg(((const float2*)(node_feat + (size_t)s0 * FEAT)) + lane);
            accx = fmaf(ns0, v0.x, accx);
            accy = fmaf(ns0, v0.y, accy);
            s0 = s1; ns0 = ns1;
            ++e;
        }
        const float2 v0 = __ldg(((const float2*)(node_feat + (size_t)s0 * FEAT)) + lane);
        accx = fmaf(ns0, v0.x, accx);
        accy = fmaf(ns0, v0.y, accy);
    }

    const float nd = rsqrtf(__ldg(&degrees[warp_id]));
    float2 r;
    r.x = accx * nd;
    r.y = accy * nd;
    ((float2*)out)[(size_t)warp_id * (FEAT / 2) + lane] = r;
}

extern "C" void kernel_launch(void* const* d_in, const int* in_sizes, int n_in,
                              void* d_out, int out_size)
{
    // Inputs per metadata order: row_ptr (int32, N+1), col_idx (int32, E),
    // node_feat (fp32, N*64), degrees (fp32, N). Output: fp32 N*64.
    const int*   row_ptr   = (const int*)d_in[0];
    const int*   col_idx   = (const int*)d_in[1];
    const float* node_feat = (const float*)d_in[2];
    const float* degrees   = (const float*)d_in[3];
    float* out = (float*)d_out;

    const int n_nodes = in_sizes[0] - 1;
    const int blocks = (n_nodes + WARPS_PER_BLOCK - 1) / WARPS_PER_BLOCK;
    gcn_agg_kernel<<<blocks, THREADS>>>(row_ptr, col_idx, node_feat, degrees,
                                        out, n_nodes);
}

// round 2
// speedup vs baseline: 1.0776x; 1.0776x over previous
#include <cuda_runtime.h>

// GCN symmetric-normalized CSR aggregation.
// out[d,:] = rsqrt(deg[d]) * sum_{e in row d} rsqrt(deg[col[e]]) * feat[col[e],:]
//
// One warp per destination node.
//  - Indices/norms for up to 32 edges are loaded in parallel (one per lane),
//    then broadcast per-edge via shfl: no serial col->deg->rsqrt chain.
//  - The warp is split into two half-warps of 16 lanes; each half gathers a
//    DIFFERENT edge's 256B feature row as 16 x float4. With a 2x unroll and
//    dual accumulators, 4 independent 256B gathers are in flight per step.

#define FEAT 64
#define WARPS_PER_BLOCK 8
#define THREADS (WARPS_PER_BLOCK * 32)
#define FULL 0xffffffffu

__global__ __launch_bounds__(THREADS) void gcn_agg_kernel(
    const int* __restrict__ row_ptr,
    const int* __restrict__ col_idx,
    const float* __restrict__ node_feat,
    const float* __restrict__ degrees,
    float* __restrict__ out,
    int n_nodes)
{
    const int warp_id = (blockIdx.x * WARPS_PER_BLOCK) + (threadIdx.x >> 5);
    const int lane = threadIdx.x & 31;
    if (warp_id >= n_nodes) return;

    const int half = lane >> 4;    // 0 or 1: which edge of the pair this lane works
    const int fl   = lane & 15;    // float4 slot within the 64-float feature row

    const int start = __ldg(&row_ptr[warp_id]);
    const int deg   = __ldg(&row_ptr[warp_id + 1]) - start;

    float4 acc0 = make_float4(0.f, 0.f, 0.f, 0.f);
    float4 acc1 = make_float4(0.f, 0.f, 0.f, 0.f);

    for (int base = 0; base < deg; base += 32) {
        // Parallel batch load of up to 32 (src, norm) pairs — one per lane.
        const int mye = base + lane;
        int   s  = 0;
        float ns = 0.f;
        if (mye < deg) {
            s  = __ldg(&col_idx[start + mye]);
            ns = rsqrtf(__ldg(&degrees[s]));
        }
        const int cnt = min(32, deg - base);

        // 4 edges per iteration: halves take (j+half) and (j+2+half).
        for (int j = 0; j < cnt; j += 4) {
            const int jj0 = j + half;
            const int jj1 = j + 2 + half;
            const int   s0 = __shfl_sync(FULL, s,  jj0 & 31);
            const float n0 = __shfl_sync(FULL, ns, jj0 & 31);
            const int   s1 = __shfl_sync(FULL, s,  jj1 & 31);
            const float n1 = __shfl_sync(FULL, ns, jj1 & 31);

            if (jj0 < cnt) {
                const float4 v = __ldg(((const float4*)(node_feat + (size_t)s0 * FEAT)) + fl);
                acc0.x = fmaf(n0, v.x, acc0.x);
                acc0.y = fmaf(n0, v.y, acc0.y);
                acc0.z = fmaf(n0, v.z, acc0.z);
                acc0.w = fmaf(n0, v.w, acc0.w);
            }
            if (jj1 < cnt) {
                const float4 v = __ldg(((const float4*)(node_feat + (size_t)s1 * FEAT)) + fl);
                acc1.x = fmaf(n1, v.x, acc1.x);
                acc1.y = fmaf(n1, v.y, acc1.y);
                acc1.z = fmaf(n1, v.z, acc1.z);
                acc1.w = fmaf(n1, v.w, acc1.w);
            }
        }
    }

    // Merge the two accumulators, then fold the two half-warps together.
    acc0.x += acc1.x; acc0.y += acc1.y; acc0.z += acc1.z; acc0.w += acc1.w;
    acc0.x += __shfl_xor_sync(FULL, acc0.x, 16);
    acc0.y += __shfl_xor_sync(FULL, acc0.y, 16);
    acc0.z += __shfl_xor_sync(FULL, acc0.z, 16);
    acc0.w += __shfl_xor_sync(FULL, acc0.w, 16);

    if (half == 0) {
        const float nd = rsqrtf(__ldg(&degrees[warp_id]));
        float4 r;
        r.x = acc0.x * nd;
        r.y = acc0.y * nd;
        r.z = acc0.z * nd;
        r.w = acc0.w * nd;
        ((float4*)out)[(size_t)warp_id * (FEAT / 4) + fl] = r;
    }
}

extern "C" void kernel_launch(void* const* d_in, const int* in_sizes, int n_in,
                              void* d_out, int out_size)
{
    const int*   row_ptr   = (const int*)d_in[0];
    const int*   col_idx   = (const int*)d_in[1];
    const float* node_feat = (const float*)d_in[2];
    const float* degrees   = (const float*)d_in[3];
    float* out = (float*)d_out;

    const int n_nodes = in_sizes[0] - 1;
    const int blocks = (n_nodes + WARPS_PER_BLOCK - 1) / WARPS_PER_BLOCK;
    gcn_agg_kernel<<<blocks, THREADS>>>(row_ptr, col_idx, node_feat, degrees,
                                        out, n_nodes);
}